// round 1
// baseline (speedup 1.0000x reference)
#include <cuda_runtime.h>
#include <cuda_bf16.h>
#include <cstdint>

// ============================================================================
// BQQLinear collapsed to:  out = quant8(x) @ W + bias
// where W[(k,n),(j,m)] is built from Y_fp/Z_fp sign structure + A coefficients.
//
// Shapes: p=2, j=32, k=32, m=32, l=8, n=32
//   x:    (2,1024, 1024)  -> X (M=2048, K=1024)
//   W:    (K=1024, N=1024),  N index = j*32+m, K index = k*32+n
//   out:  (M=2048, N=1024) fp32
// ============================================================================

#define PP 2
#define JJ 32
#define KK 32
#define MM 32
#define LL 8
#define NN 32

#define GEMM_M 2048
#define GEMM_N 1024
#define GEMM_K 1024

// 4 MB scratch for the effective weight matrix (allocation-free scratch rule).
__device__ float g_W[GEMM_K * GEMM_N];

__device__ __forceinline__ float sgnf(float v) {
    return (v > 0.f) ? 1.f : ((v < 0.f) ? -1.f : 0.f);
}

// ----------------------------------------------------------------------------
// Kernel 1: build W. One block per (j,k) pair; 256 threads.
//   W[(k*32+n)*1024 + (j*32+m)] =
//     sum_p [ A0*ys*zs * (sum_l sgnY[m,l]*sgnZ[l,n])
//           + A1*ys * (sum_l sgnY[m,l])
//           + A2*zs * (sum_l sgnZ[l,n])
//           + A3 ]
//   ys = mean|Y_fp[p,j,k,:,:]| (m*l = 256), zs = mean|Z_fp[p,j,k,:,:]| (l*n = 256)
// ----------------------------------------------------------------------------
__global__ __launch_bounds__(256) void build_w_kernel(
    const float* __restrict__ Y,   // (p,j,k,m,l)
    const float* __restrict__ Z,   // (p,j,k,l,n)
    const float* __restrict__ A)   // (p,j,k,4)
{
    const int j = blockIdx.x;
    const int k = blockIdx.y;
    const int tid = threadIdx.x;   // 0..255

    __shared__ float sY[PP][MM * LL];   // sign(Y), index m*8+l
    __shared__ float sZ[PP][LL * NN];   // sign(Z), index l*32+n
    __shared__ float redY[256], redZ[256];
    __shared__ float ysh[PP], zsh[PP];
    __shared__ float aSh[PP][4];
    __shared__ float Ysum[PP][MM];      // sum_l sgnY[m,l]
    __shared__ float Zsum[PP][NN];      // sum_l sgnZ[l,n]

    #pragma unroll
    for (int p = 0; p < PP; ++p) {
        size_t base = ((size_t)((p * JJ + j) * KK + k)) * 256;
        float y = Y[base + tid];
        float z = Z[base + tid];
        sY[p][tid] = sgnf(y);
        sZ[p][tid] = sgnf(z);
        redY[tid] = fabsf(y);
        redZ[tid] = fabsf(z);
        __syncthreads();
        #pragma unroll
        for (int s = 128; s > 0; s >>= 1) {
            if (tid < s) { redY[tid] += redY[tid + s]; redZ[tid] += redZ[tid + s]; }
            __syncthreads();
        }
        if (tid == 0) {
            ysh[p] = redY[0] * (1.0f / 256.0f);
            zsh[p] = redZ[0] * (1.0f / 256.0f);
        }
        __syncthreads();
    }

    if (tid < PP * 4) {
        int p = tid >> 2, c = tid & 3;
        aSh[p][c] = A[((size_t)(p * JJ + j) * KK + k) * 4 + c];
    }
    if (tid < 64) {
        int p = tid >> 5, m = tid & 31;
        float s = 0.f;
        #pragma unroll
        for (int l = 0; l < LL; ++l) s += sY[p][m * LL + l];
        Ysum[p][m] = s;
    } else if (tid < 128) {
        int t = tid - 64;
        int p = t >> 5, n = t & 31;
        float s = 0.f;
        #pragma unroll
        for (int l = 0; l < LL; ++l) s += sZ[p][l * NN + n];
        Zsum[p][n] = s;
    }
    __syncthreads();

    // 1024 (n,m) entries, 4 per thread; consecutive tid -> consecutive m (coalesced store)
    #pragma unroll
    for (int t = 0; t < 4; ++t) {
        int idx = t * 256 + tid;
        int n = idx >> 5;
        int m = idx & 31;
        float w = 0.f;
        #pragma unroll
        for (int p = 0; p < PP; ++p) {
            float dot = 0.f;
            #pragma unroll
            for (int l = 0; l < LL; ++l)
                dot += sY[p][m * LL + l] * sZ[p][l * NN + n];
            float ys = ysh[p], zs = zsh[p];
            w += aSh[p][0] * ys * zs * dot
               + aSh[p][1] * ys * Ysum[p][m]
               + aSh[p][2] * zs * Zsum[p][n]
               + aSh[p][3];
        }
        g_W[(size_t)(k * NN + n) * GEMM_N + (j * MM + m)] = w;
    }
}

// ----------------------------------------------------------------------------
// Kernel 2: SGEMM  out[M,N] = quant8(X)[M,K] @ W[K,N] + bias[N]
// Tiles: BM=128, BN=128, BK=8; 256 threads; 8x8 microtile per thread.
// quant8 fused into A-tile load; bias fused into epilogue.
// ----------------------------------------------------------------------------
__global__ __launch_bounds__(256) void gemm_kernel(
    const float* __restrict__ X,          // (M, K)
    const float* __restrict__ bias,       // (N)
    const float* __restrict__ act_scale,  // (1)
    float* __restrict__ out)              // (M, N)
{
    const int bx = blockIdx.x;   // N tile (0..7)
    const int by = blockIdx.y;   // M tile (0..15)
    const int tid = threadIdx.x;

    __shared__ float As[8][128];   // [k][m]
    __shared__ float Bs[8][128];   // [k][n]

    const float s = fmaxf(fabsf(act_scale[0]), 1e-8f);
    const float inv_s = 1.0f / s;

    // A-tile load mapping: 128 rows (M) x 8 cols (K); 2 float4 per row
    const int aRow = tid >> 1;            // 0..127
    const int aCol = (tid & 1) << 2;      // 0 or 4
    // B-tile load mapping: 8 rows (K) x 128 cols (N); float4 each
    const int bRow = tid >> 5;            // 0..7
    const int bCol = (tid & 31) << 2;     // 0..124

    const float* Aptr = X + (size_t)(by * 128 + aRow) * GEMM_K + aCol;
    const float* Bptr = g_W + (size_t)bRow * GEMM_N + bx * 128 + bCol;

    const int ty = (tid >> 4) << 3;       // 0..120 step 8
    const int tx = (tid & 15) << 3;       // 0..120 step 8

    float acc[8][8];
    #pragma unroll
    for (int i = 0; i < 8; ++i)
        #pragma unroll
        for (int jn = 0; jn < 8; ++jn) acc[i][jn] = 0.f;

    for (int k0 = 0; k0 < GEMM_K; k0 += 8) {
        float4 av = *(const float4*)(Aptr + k0);
        // quant8: q = clip(rint(x/s), -127, 127); X = q*s  (rintf = half-to-even)
        float q0 = fminf(fmaxf(rintf(av.x * inv_s), -127.f), 127.f) * s;
        float q1 = fminf(fmaxf(rintf(av.y * inv_s), -127.f), 127.f) * s;
        float q2 = fminf(fmaxf(rintf(av.z * inv_s), -127.f), 127.f) * s;
        float q3 = fminf(fmaxf(rintf(av.w * inv_s), -127.f), 127.f) * s;
        As[aCol + 0][aRow] = q0;
        As[aCol + 1][aRow] = q1;
        As[aCol + 2][aRow] = q2;
        As[aCol + 3][aRow] = q3;

        *(float4*)&Bs[bRow][bCol] = *(const float4*)(Bptr + (size_t)k0 * GEMM_N);
        __syncthreads();

        #pragma unroll
        for (int kk = 0; kk < 8; ++kk) {
            float ar[8], br[8];
            *(float4*)&ar[0] = *(const float4*)&As[kk][ty];
            *(float4*)&ar[4] = *(const float4*)&As[kk][ty + 4];
            *(float4*)&br[0] = *(const float4*)&Bs[kk][tx];
            *(float4*)&br[4] = *(const float4*)&Bs[kk][tx + 4];
            #pragma unroll
            for (int i = 0; i < 8; ++i)
                #pragma unroll
                for (int jn = 0; jn < 8; ++jn)
                    acc[i][jn] += ar[i] * br[jn];
        }
        __syncthreads();
    }

    // Epilogue: add bias, write out
    #pragma unroll
    for (int i = 0; i < 8; ++i) {
        float* orow = out + (size_t)(by * 128 + ty + i) * GEMM_N + bx * 128 + tx;
        const float* brow = bias + bx * 128 + tx;
        #pragma unroll
        for (int jn = 0; jn < 8; ++jn)
            orow[jn] = acc[i][jn] + brow[jn];
    }
}

// ----------------------------------------------------------------------------
// Launch
// Inputs (metadata order): x, Y_fp, Z_fp, A, bias, act_scale
// ----------------------------------------------------------------------------
extern "C" void kernel_launch(void* const* d_in, const int* in_sizes, int n_in,
                              void* d_out, int out_size) {
    const float* x         = (const float*)d_in[0];
    const float* Y_fp      = (const float*)d_in[1];
    const float* Z_fp      = (const float*)d_in[2];
    const float* A         = (const float*)d_in[3];
    const float* bias      = (const float*)d_in[4];
    const float* act_scale = (const float*)d_in[5];
    float* out = (float*)d_out;

    dim3 gridW(JJ, KK);
    build_w_kernel<<<gridW, 256>>>(Y_fp, Z_fp, A);

    dim3 gridG(GEMM_N / 128, GEMM_M / 128);
    gemm_kernel<<<gridG, 256>>>(x, bias, act_scale, out);
}